// round 7
// baseline (speedup 1.0000x reference)
#include <cuda_runtime.h>

// Problem constants (fixed by the reference)
#define DVOL   128
#define RES    179
#define NPROJ  10
#define PIX    (RES * RES)          // 32041
#define NPIX   (NPROJ * PIX)        // 320410
#define BW2    134                  // padded extent of zi/xi (0..133), z0 = zi-3
#define BPL2   (BW2 * BW2)          // 17956 entries per k-plane
#define ETOT   (DVOL * BPL2)        // 2,298,368 entries
#define NGRP   ((NPIX + 31) / 32)   // 10013 pixel groups of 32

#define MAGIC      8388608.0f       // 2^23
#define MAGICH     8388607.5f       // 2^23 - 0.5  (floor via RNE(g - 0.5))
// bits(2^23 + n) = 0x4B000000 + n  for integer n in [0, 2^23)
// off = bits(mz)*134 + bits(mx) = zi*134 + xi + 0x8D000000  (mod 2^32, no carry)
#define OFF_BIAS   0x8D000000u

// Bilinear-coefficient table (zero guard band of 3 on each side):
//   E[k][zi][xi] = ( c00, c01-c00, c10-c00, c11-c01-c10+c00 )
// with c_ab = A[z0+a][x0+b], z0 = zi-3, x0 = xi-3,
//      A[z][x] = 0.5*(vol[z][k-1][x] + vol[z][k][x])  (vol[.,-1,.] = 0),
//      A = 0 outside z,x in [0,127].
// sample = e0 + wx*e1 + wz*(e2 + wx*e3)
__device__ float4 g_E[ETOT];        // ~36.8 MB (L2-resident)

__global__ void __launch_bounds__(256) build_E_kernel(const float* __restrict__ vol) {
    int t = blockIdx.x * blockDim.x + threadIdx.x;
    if (t >= ETOT) return;
    int k   = t / BPL2;
    int rem = t - k * BPL2;
    int zi  = rem / BW2;
    int xi  = rem - zi * BW2;
    int z0  = zi - 3;
    int x0  = xi - 3;
    bool hk = (k > 0);
    int km  = hk ? k - 1 : 0;

    float c00 = 0.f, c01 = 0.f, c10 = 0.f, c11 = 0.f;
    {
        int z = z0;
        if ((unsigned)z < 128u) {
            const float* pk = vol + (z * DVOL + k)  * DVOL;
            const float* pm = vol + (z * DVOL + km) * DVOL;
            if ((unsigned)x0       < 128u) c00 = 0.5f * (__ldg(pk + x0)     + (hk ? __ldg(pm + x0)     : 0.f));
            if ((unsigned)(x0 + 1) < 128u) c01 = 0.5f * (__ldg(pk + x0 + 1) + (hk ? __ldg(pm + x0 + 1) : 0.f));
        }
    }
    {
        int z = z0 + 1;
        if ((unsigned)z < 128u) {
            const float* pk = vol + (z * DVOL + k)  * DVOL;
            const float* pm = vol + (z * DVOL + km) * DVOL;
            if ((unsigned)x0       < 128u) c10 = 0.5f * (__ldg(pk + x0)     + (hk ? __ldg(pm + x0)     : 0.f));
            if ((unsigned)(x0 + 1) < 128u) c11 = 0.5f * (__ldg(pk + x0 + 1) + (hk ? __ldg(pm + x0 + 1) : 0.f));
        }
    }
    g_E[t] = make_float4(c00, c01 - c00, c10 - c00, c11 - c01 - c10 + c00);
}

// ── packed f32x2 helpers ────────────────────────────────────────────────────
typedef unsigned long long u64;

__device__ __forceinline__ u64 pack2(float lo, float hi) {
    u64 r;
    asm("mov.b64 %0, {%1, %2};" : "=l"(r) : "f"(lo), "f"(hi));
    return r;
}
__device__ __forceinline__ u64 add2(u64 a, u64 b) {
    u64 r;
    asm("add.rn.f32x2 %0, %1, %2;" : "=l"(r) : "l"(a), "l"(b));
    return r;
}
__device__ __forceinline__ u64 fma2(u64 a, u64 b, u64 c) {
    u64 r;
    asm("fma.rn.f32x2 %0, %1, %2, %3;" : "=l"(r) : "l"(a), "l"(b), "l"(c));
    return r;
}
__device__ __forceinline__ void unpack2f(u64 v, float &lo, float &hi) {
    asm("mov.b64 {%0, %1}, %2;" : "=f"(lo), "=f"(hi) : "l"(v));
}
__device__ __forceinline__ void unpack2u(u64 v, unsigned &lo, unsigned &hi) {
    asm("mov.b64 {%0, %1}, %2;" : "=r"(lo), "=r"(hi) : "l"(v));
}

// Block = 128 threads = 32 pixels (one per lane) x 4 k-quarters (one per warp).
__global__ void __launch_bounds__(128) project_kernel(
    const float* __restrict__ poses,
    const int*   __restrict__ idx,
    float*       __restrict__ out,
    int tail)
{
    __shared__ float part[4][33];

    int g = blockIdx.x;
    if (g == NGRP) {                 // dedicated tail block: write idx appendix
        for (int u = threadIdx.x; u < tail; u += 128)
            out[NPIX + u] = (u < NPROJ) ? (float)__ldg(&idx[u]) : 0.0f;
        return;
    }

    int lane = threadIdx.x & 31;
    int q    = threadIdx.x >> 5;     // k-quarter

    int p_pix = g * 32 + lane;
    bool valid = p_pix < NPIX;
    int pp  = valid ? p_pix : NPIX - 1;
    int p   = pp / PIX;
    int rem = pp - p * PIX;
    int i   = rem / RES;             // detector row (gx)
    int j   = rem - i * RES;         // detector col (gy) — contiguous per lane

    int e = __ldg(&idx[p]);
    float ex = __ldg(&poses[e * 3 + 0]);
    float ey = __ldg(&poses[e * 3 + 1]);
    float ez = __ldg(&poses[e * 3 + 2]);

    float gx = (float)i - 89.5f;
    float gy = (float)j - 89.5f;

    // Unnormalized ray; normalization cancels except in the dx weight.
    float rx = gx - ex;
    float ry = -ey;                  // detector plane is y = 0
    float rz = gy - ez;
    float n  = sqrtf(rx * rx + ry * ry + rz * rz);
    float inv_ry = __fdividef(1.0f, ry);
    float dxw = fabsf(inv_ry) * n;

    // Sample position at plane k (volume index space), linear in k.
    float sz = rx * inv_ry;
    float sx = rz * inv_ry;
    float bz = fmaf(-ey, sz, ex + 63.5f);
    float bx = fmaf(-ey, sx, ez + 63.5f);

    // Restrictive trim to fz,fx in [-2.5, 130.5]; the 3-wide zero guard band
    // makes the loop branch-free; dropped samples are exactly zero.
    float lo_k = 0.0f, hi_k = 127.0f;
    {
        if (fabsf(sz) > 1e-12f) {
            float is = __fdividef(1.0f, sz);
            float t0 = (-2.5f - bz) * is, t1 = (130.5f - bz) * is;
            lo_k = fmaxf(lo_k, fminf(t0, t1));
            hi_k = fminf(hi_k, fmaxf(t0, t1));
        } else if (bz < -2.5f || bz > 130.5f) { lo_k = 1.0f; hi_k = 0.0f; }
        if (fabsf(sx) > 1e-12f) {
            float is = __fdividef(1.0f, sx);
            float t0 = (-2.5f - bx) * is, t1 = (130.5f - bx) * is;
            lo_k = fmaxf(lo_k, fminf(t0, t1));
            hi_k = fminf(hi_k, fmaxf(t0, t1));
        } else if (bx < -2.5f || bx > 130.5f) { lo_k = 1.0f; hi_k = 0.0f; }
    }
    int kmin = max(0, (int)ceilf(lo_k));
    int kmax = min(DVOL - 1, (int)floorf(hi_k));

    // This warp's k-quarter
    int qlo = max(kmin, q * 32);
    int qhi = min(kmax, q * 32 + 31);

    // Shifted coordinates: fz',fx' in [0.5, 133.5].
    u64 S2  = pack2(sz, sx);
    u64 B2  = pack2(bz + 3.0f, bx + 3.0f);
    u64 KF2 = pack2((float)qlo, (float)qlo);
    const u64 ONE2     = pack2(1.0f, 1.0f);
    const u64 NEGONE2  = pack2(-1.0f, -1.0f);
    const u64 MAGICH2  = pack2(MAGICH, MAGICH);
    const u64 NEGMAG2  = pack2(-MAGIC, -MAGIC);

    // Bias-folded base pointer: off = bits(mz)*134 + bits(mx)
    //                               = zi*134 + xi + OFF_BIAS  (exact, no carry)
    const char* bias_base = (const char*)g_E
                          + (size_t)qlo * (BPL2 * 16)
                          - ((size_t)OFF_BIAS << 4);

    float accA = 0.0f, accB = 0.0f;
    int k = qlo;

    // Batched-by-4: packed address gen, 4 independent LDG.128s, then math.
    for (; k + 3 <= qhi; k += 4, bias_base += 4 * (BPL2 * 16)) {
        unsigned offv[4];
        float wzv[4], wxv[4];
        #pragma unroll
        for (int u = 0; u < 4; ++u) {
            u64 P = fma2(KF2, S2, B2);          // (fz', fx')
            KF2   = add2(KF2, ONE2);            // exact integer step
            u64 M = add2(P, MAGICH2);           // 2^23 + floor(.)
            u64 T = add2(M, NEGMAG2);           // (floor fz', floor fx') as floats
            u64 W = fma2(T, NEGONE2, P);        // fractional weights
            unsigned mzb, mxb;
            unpack2u(M, mzb, mxb);
            offv[u] = mzb * (unsigned)BW2 + mxb;   // zi*134+xi+BIAS (mod 2^32)
            unpack2f(W, wzv[u], wxv[u]);
        }
        float4 cv[4];
        #pragma unroll
        for (int u = 0; u < 4; ++u)
            cv[u] = __ldg((const float4*)(bias_base + (size_t)u * (BPL2 * 16)
                                          + ((size_t)offv[u] << 4)));
        #pragma unroll
        for (int u = 0; u < 4; ++u) {
            float t0 = fmaf(wxv[u], cv[u].y, cv[u].x);
            float t1 = fmaf(wxv[u], cv[u].w, cv[u].z);
            accA += t0;
            accB  = fmaf(wzv[u], t1, accB);
        }
    }
    for (; k <= qhi; ++k, bias_base += (BPL2 * 16)) {
        u64 P = fma2(KF2, S2, B2);
        KF2   = add2(KF2, ONE2);
        u64 M = add2(P, MAGICH2);
        u64 T = add2(M, NEGMAG2);
        u64 W = fma2(T, NEGONE2, P);
        unsigned mzb, mxb;
        unpack2u(M, mzb, mxb);
        unsigned off = mzb * (unsigned)BW2 + mxb;
        float wz, wx;
        unpack2f(W, wz, wx);
        float4 c = __ldg((const float4*)(bias_base + ((size_t)off << 4)));
        float t0 = fmaf(wx, c.y, c.x);
        float t1 = fmaf(wx, c.w, c.z);
        accA += t0;
        accB  = fmaf(wz, t1, accB);
    }

    part[q][lane] = accA + accB;
    __syncthreads();

    if (q == 0 && valid) {
        float s = part[0][lane] + part[1][lane] + part[2][lane] + part[3][lane];
        out[p_pix] = s * dxw;
    }
}

extern "C" void kernel_launch(void* const* d_in, const int* in_sizes, int n_in,
                              void* d_out, int out_size) {
    const float* vol   = (const float*)d_in[0];   // I_rec: 1*1*128*128*128 f32
    const float* poses = (const float*)d_in[1];   // 50*3 f32
    const int*   idx   = (const int*)d_in[2];     // 10 i32
    float* out = (float*)d_out;

    build_E_kernel<<<(ETOT + 255) / 256, 256>>>(vol);

    int tail = out_size - NPIX;
    if (tail < 0) tail = 0;
    if (tail > 1024) tail = 1024;
    project_kernel<<<NGRP + 1, 128>>>(poses, idx, out, tail);
}

// round 8
// speedup vs baseline: 1.2086x; 1.2086x over previous
#include <cuda_runtime.h>

// Problem constants (fixed by the reference)
#define DVOL   128
#define RES    179
#define NPROJ  10
#define PIX    (RES * RES)          // 32041
#define NPIX   (NPROJ * PIX)        // 320410
#define BW2    134                  // padded extent of zi/xi (0..133), z0 = zi-3
#define BPL2   (BW2 * BW2)          // 17956 entries per k-plane
#define ETOT   (DVOL * BPL2)        // 2,298,368 entries
#define NGRP   ((NPIX + 31) / 32)   // 10013 pixel groups of 32

#define MAGIC      8388608.0f       // 2^23
#define MAGICH     8388607.5f       // 2^23 - 0.5  (floor via RNE(g - 0.5))
// bits(2^23 + n) = 0x4B000000 + n for integer n in [0,2^23).
// bits(mz)*134 + bits(mx) = zi*134 + xi + 0x4B000000*135 (mod 2^32)
//                         = zi*134 + xi + 0x8D000000   (no carry: zi*134+xi < 2^15)
#define OFF_BIAS   0x8D000000u

// Bilinear-coefficient table (zero guard band of 3 on each side):
//   E[k][zi][xi] = ( c00, c01-c00, c10-c00, c11-c01-c10+c00 )
// with c_ab = A[z0+a][x0+b], z0 = zi-3, x0 = xi-3,
//      A[z][x] = 0.5*(vol[z][k-1][x] + vol[z][k][x])  (vol[.,-1,.] = 0),
//      A = 0 outside z,x in [0,127].
// sample = e0 + wx*e1 + wz*(e2 + wx*e3)
__device__ float4 g_E[ETOT];        // ~36.8 MB (L2-resident)

__global__ void __launch_bounds__(256) build_E_kernel(const float* __restrict__ vol) {
    int t = blockIdx.x * blockDim.x + threadIdx.x;
    if (t >= ETOT) return;
    int k   = t / BPL2;
    int rem = t - k * BPL2;
    int zi  = rem / BW2;
    int xi  = rem - zi * BW2;
    int z0  = zi - 3;
    int x0  = xi - 3;
    bool hk = (k > 0);
    int km  = hk ? k - 1 : 0;

    float c00 = 0.f, c01 = 0.f, c10 = 0.f, c11 = 0.f;
    {
        int z = z0;
        if ((unsigned)z < 128u) {
            const float* pk = vol + (z * DVOL + k)  * DVOL;
            const float* pm = vol + (z * DVOL + km) * DVOL;
            if ((unsigned)x0       < 128u) c00 = 0.5f * (__ldg(pk + x0)     + (hk ? __ldg(pm + x0)     : 0.f));
            if ((unsigned)(x0 + 1) < 128u) c01 = 0.5f * (__ldg(pk + x0 + 1) + (hk ? __ldg(pm + x0 + 1) : 0.f));
        }
    }
    {
        int z = z0 + 1;
        if ((unsigned)z < 128u) {
            const float* pk = vol + (z * DVOL + k)  * DVOL;
            const float* pm = vol + (z * DVOL + km) * DVOL;
            if ((unsigned)x0       < 128u) c10 = 0.5f * (__ldg(pk + x0)     + (hk ? __ldg(pm + x0)     : 0.f));
            if ((unsigned)(x0 + 1) < 128u) c11 = 0.5f * (__ldg(pk + x0 + 1) + (hk ? __ldg(pm + x0 + 1) : 0.f));
        }
    }
    g_E[t] = make_float4(c00, c01 - c00, c10 - c00, c11 - c01 - c10 + c00);
}

// Block = 128 threads = 32 pixels (one per lane) x 4 balanced k-chunks (one per warp).
__global__ void __launch_bounds__(128) project_kernel(
    const float* __restrict__ poses,
    const int*   __restrict__ idx,
    float*       __restrict__ out,
    int tail)
{
    __shared__ float part[4][33];

    int g = blockIdx.x;
    if (g == NGRP) {                 // dedicated tail block: write idx appendix
        for (int u = threadIdx.x; u < tail; u += 128)
            out[NPIX + u] = (u < NPROJ) ? (float)__ldg(&idx[u]) : 0.0f;
        return;
    }

    int lane = threadIdx.x & 31;
    int q    = threadIdx.x >> 5;     // k-chunk index

    int p_pix = g * 32 + lane;
    bool valid = p_pix < NPIX;
    int pp  = valid ? p_pix : NPIX - 1;
    int p   = pp / PIX;
    int rem = pp - p * PIX;
    int i   = rem / RES;             // detector row (gx)
    int j   = rem - i * RES;         // detector col (gy) — contiguous per lane

    int e = __ldg(&idx[p]);
    float ex = __ldg(&poses[e * 3 + 0]);
    float ey = __ldg(&poses[e * 3 + 1]);
    float ez = __ldg(&poses[e * 3 + 2]);

    float gx = (float)i - 89.5f;
    float gy = (float)j - 89.5f;

    // Unnormalized ray; normalization cancels except in the dx weight.
    float rx = gx - ex;
    float ry = -ey;                  // detector plane is y = 0
    float rz = gy - ez;
    float n  = sqrtf(rx * rx + ry * ry + rz * rz);
    float inv_ry = __fdividef(1.0f, ry);
    float dxw = fabsf(inv_ry) * n;

    // Sample position at plane k (volume index space), linear in k.
    float sz = rx * inv_ry;
    float sx = rz * inv_ry;
    float bz = fmaf(-ey, sz, ex + 63.5f);
    float bx = fmaf(-ey, sx, ez + 63.5f);

    // Trim to fz,fx in [-1, 128]: outside this, BOTH stencil rows/cols hit the
    // zero-padded region, so dropped samples contribute exactly zero. Float
    // slop (~1e-5) only moves us within the 3-wide guard band (safe).
    float lo_k = 0.0f, hi_k = 127.0f;
    {
        if (fabsf(sz) > 1e-12f) {
            float is = __fdividef(1.0f, sz);
            float t0 = (-1.0f - bz) * is, t1 = (128.0f - bz) * is;
            lo_k = fmaxf(lo_k, fminf(t0, t1));
            hi_k = fminf(hi_k, fmaxf(t0, t1));
        } else if (bz < -1.0f || bz > 128.0f) { lo_k = 1.0f; hi_k = 0.0f; }
        if (fabsf(sx) > 1e-12f) {
            float is = __fdividef(1.0f, sx);
            float t0 = (-1.0f - bx) * is, t1 = (128.0f - bx) * is;
            lo_k = fmaxf(lo_k, fminf(t0, t1));
            hi_k = fminf(hi_k, fmaxf(t0, t1));
        } else if (bx < -1.0f || bx > 128.0f) { lo_k = 1.0f; hi_k = 0.0f; }
    }
    int kmin = max(0, (int)ceilf(lo_k));
    int kmax = min(DVOL - 1, (int)floorf(hi_k));

    // Balanced split of [kmin, kmax] across the 4 warps.
    int len   = kmax - kmin + 1;           // may be <= 0
    int chunk = (len + 3) >> 2;
    int qlo   = kmin + q * chunk;
    int qhi   = min(qlo + chunk - 1, kmax);

    // Shifted coordinates: fz' = fz + 3 in [2, 131] (magic-safe).
    float bzp = bz + 3.0f;
    float bxp = bx + 3.0f;

    // Bias-folded base pointer (see OFF_BIAS derivation above).
    const char* bias_base = (const char*)g_E
                          + (size_t)qlo * (size_t)(BPL2 * 16)
                          - ((size_t)OFF_BIAS << 4);

    float accA = 0.0f, accB = 0.0f;
    float kf = (float)qlo;
    int k = qlo;

    // Batched-by-4: address gen (full-rate FADD/FFMA/IMAD only), then 4
    // independent LDG.128s, then math.
    for (; k + 3 <= qhi; k += 4, bias_base += 4 * (size_t)(BPL2 * 16)) {
        unsigned offv[4];
        float wzv[4], wxv[4];
        #pragma unroll
        for (int u = 0; u < 4; ++u) {
            float fzp = fmaf(kf, sz, bzp);
            float fxp = fmaf(kf, sx, bxp);
            kf += 1.0f;
            float mz = fzp + MAGICH;           // 2^23 + floor(fz')
            float mx = fxp + MAGICH;
            unsigned mzb = (unsigned)__float_as_int(mz);
            unsigned mxb = (unsigned)__float_as_int(mx);
            wzv[u] = fzp - (mz - MAGIC);
            wxv[u] = fxp - (mx - MAGIC);
            offv[u] = mzb * (unsigned)BW2 + mxb;   // zi*134+xi+OFF_BIAS (mod 2^32)
        }
        float4 cv[4];
        #pragma unroll
        for (int u = 0; u < 4; ++u)
            cv[u] = __ldg((const float4*)(bias_base + (size_t)u * (BPL2 * 16)
                                          + ((size_t)offv[u] << 4)));
        #pragma unroll
        for (int u = 0; u < 4; ++u) {
            float t0 = fmaf(wxv[u], cv[u].y, cv[u].x);
            float t1 = fmaf(wxv[u], cv[u].w, cv[u].z);
            accA += t0;
            accB  = fmaf(wzv[u], t1, accB);
        }
    }
    for (; k <= qhi; ++k, bias_base += (size_t)(BPL2 * 16)) {
        float fzp = fmaf(kf, sz, bzp);
        float fxp = fmaf(kf, sx, bxp);
        kf += 1.0f;
        float mz = fzp + MAGICH;
        float mx = fxp + MAGICH;
        unsigned mzb = (unsigned)__float_as_int(mz);
        unsigned mxb = (unsigned)__float_as_int(mx);
        float wz = fzp - (mz - MAGIC);
        float wx = fxp - (mx - MAGIC);
        unsigned off = mzb * (unsigned)BW2 + mxb;
        float4 c = __ldg((const float4*)(bias_base + ((size_t)off << 4)));
        float t0 = fmaf(wx, c.y, c.x);
        float t1 = fmaf(wx, c.w, c.z);
        accA += t0;
        accB  = fmaf(wz, t1, accB);
    }

    part[q][lane] = accA + accB;
    __syncthreads();

    if (q == 0 && valid) {
        float s = part[0][lane] + part[1][lane] + part[2][lane] + part[3][lane];
        out[p_pix] = s * dxw;
    }
}

extern "C" void kernel_launch(void* const* d_in, const int* in_sizes, int n_in,
                              void* d_out, int out_size) {
    const float* vol   = (const float*)d_in[0];   // I_rec: 1*1*128*128*128 f32
    const float* poses = (const float*)d_in[1];   // 50*3 f32
    const int*   idx   = (const int*)d_in[2];     // 10 i32
    float* out = (float*)d_out;

    build_E_kernel<<<(ETOT + 255) / 256, 256>>>(vol);

    int tail = out_size - NPIX;
    if (tail < 0) tail = 0;
    if (tail > 1024) tail = 1024;
    project_kernel<<<NGRP + 1, 128>>>(poses, idx, out, tail);
}

// round 9
// speedup vs baseline: 1.2249x; 1.0136x over previous
#include <cuda_runtime.h>
#include <cuda_fp16.h>

// Problem constants (fixed by the reference)
#define DVOL   128
#define RES    179
#define NPROJ  10
#define PIX    (RES * RES)          // 32041
#define NPIX   (NPROJ * PIX)        // 320410
#define BW2    134                  // padded extent of zi/xi (0..133), z0 = zi-3
#define BPL2   (BW2 * BW2)          // 17956 entries per k-plane
#define ETOT   (DVOL * BPL2)        // 2,298,368 entries
#define NGRP   ((NPIX + 31) / 32)   // 10013 pixel groups of 32

#define MAGIC      8388608.0f       // 2^23
#define MAGICH     8388607.5f       // 2^23 - 0.5  (floor via RNE(g - 0.5))
// bits(2^23 + n) = 0x4B000000 + n for integer n in [0,2^23).
// bits(mz)*134 + bits(mx) = zi*134 + xi + 0x8D000000 (mod 2^32, no carry).
#define OFF_BIAS   0x8D000000u

// fp16 bilinear-coefficient table (zero guard band of 3 on each side):
//   entry.x = half2(e0, e2), entry.y = half2(e1, e3)
//   e0=c00, e1=c01-c00, e2=c10-c00, e3=c11-c01-c10+c00
// with c_ab = A[z0+a][x0+b], z0 = zi-3, x0 = xi-3,
//      A[z][x] = 0.5*(vol[z][k-1][x] + vol[z][k][x]) (vol[.,-1,.] = 0),
//      A = 0 outside z,x in [0,127].
// sample = (e0 + wx*e1) + wz*(e2 + wx*e3)
__device__ uint2 g_H[ETOT];         // 128*17956*8B ≈ 18.4 MB (L2-resident)

__global__ void __launch_bounds__(256) build_H_kernel(const float* __restrict__ vol) {
    int t = blockIdx.x * blockDim.x + threadIdx.x;
    if (t >= ETOT) return;
    int k   = t / BPL2;
    int rem = t - k * BPL2;
    int zi  = rem / BW2;
    int xi  = rem - zi * BW2;
    int z0  = zi - 3;
    int x0  = xi - 3;
    bool hk = (k > 0);
    int km  = hk ? k - 1 : 0;

    float c00 = 0.f, c01 = 0.f, c10 = 0.f, c11 = 0.f;
    {
        int z = z0;
        if ((unsigned)z < 128u) {
            const float* pk = vol + (z * DVOL + k)  * DVOL;
            const float* pm = vol + (z * DVOL + km) * DVOL;
            if ((unsigned)x0       < 128u) c00 = 0.5f * (__ldg(pk + x0)     + (hk ? __ldg(pm + x0)     : 0.f));
            if ((unsigned)(x0 + 1) < 128u) c01 = 0.5f * (__ldg(pk + x0 + 1) + (hk ? __ldg(pm + x0 + 1) : 0.f));
        }
    }
    {
        int z = z0 + 1;
        if ((unsigned)z < 128u) {
            const float* pk = vol + (z * DVOL + k)  * DVOL;
            const float* pm = vol + (z * DVOL + km) * DVOL;
            if ((unsigned)x0       < 128u) c10 = 0.5f * (__ldg(pk + x0)     + (hk ? __ldg(pm + x0)     : 0.f));
            if ((unsigned)(x0 + 1) < 128u) c11 = 0.5f * (__ldg(pk + x0 + 1) + (hk ? __ldg(pm + x0 + 1) : 0.f));
        }
    }
    __half2 lo = __floats2half2_rn(c00, c10 - c00);              // (e0, e2)
    __half2 hi = __floats2half2_rn(c01 - c00, c11 - c01 - c10 + c00); // (e1, e3)
    uint2 v;
    v.x = *reinterpret_cast<const unsigned int*>(&lo);
    v.y = *reinterpret_cast<const unsigned int*>(&hi);
    g_H[t] = v;
}

// Block = 128 threads = 32 pixels (one per lane) x 4 balanced k-chunks (one per warp).
__global__ void __launch_bounds__(128) project_kernel(
    const float* __restrict__ poses,
    const int*   __restrict__ idx,
    float*       __restrict__ out,
    int tail)
{
    __shared__ float part[4][33];

    int g = blockIdx.x;
    if (g == NGRP) {                 // dedicated tail block: write idx appendix
        for (int u = threadIdx.x; u < tail; u += 128)
            out[NPIX + u] = (u < NPROJ) ? (float)__ldg(&idx[u]) : 0.0f;
        return;
    }

    int lane = threadIdx.x & 31;
    int q    = threadIdx.x >> 5;     // k-chunk index

    int p_pix = g * 32 + lane;
    bool valid = p_pix < NPIX;
    int pp  = valid ? p_pix : NPIX - 1;
    int p   = pp / PIX;
    int rem = pp - p * PIX;
    int i   = rem / RES;             // detector row (gx)
    int j   = rem - i * RES;         // detector col (gy) — contiguous per lane

    int e = __ldg(&idx[p]);
    float ex = __ldg(&poses[e * 3 + 0]);
    float ey = __ldg(&poses[e * 3 + 1]);
    float ez = __ldg(&poses[e * 3 + 2]);

    float gx = (float)i - 89.5f;
    float gy = (float)j - 89.5f;

    // Unnormalized ray; normalization cancels except in the dx weight.
    float rx = gx - ex;
    float ry = -ey;                  // detector plane is y = 0
    float rz = gy - ez;
    float n  = sqrtf(rx * rx + ry * ry + rz * rz);
    float inv_ry = __fdividef(1.0f, ry);
    float dxw = fabsf(inv_ry) * n;

    // Sample position at plane k (volume index space), linear in k.
    float sz = rx * inv_ry;
    float sx = rz * inv_ry;
    float bz = fmaf(-ey, sz, ex + 63.5f);
    float bx = fmaf(-ey, sx, ez + 63.5f);

    // Trim to fz,fx in [-1, 128]: outside this both stencil rows/cols hit the
    // zero-padded region, so dropped samples contribute exactly zero.
    float lo_k = 0.0f, hi_k = 127.0f;
    {
        if (fabsf(sz) > 1e-12f) {
            float is = __fdividef(1.0f, sz);
            float t0 = (-1.0f - bz) * is, t1 = (128.0f - bz) * is;
            lo_k = fmaxf(lo_k, fminf(t0, t1));
            hi_k = fminf(hi_k, fmaxf(t0, t1));
        } else if (bz < -1.0f || bz > 128.0f) { lo_k = 1.0f; hi_k = 0.0f; }
        if (fabsf(sx) > 1e-12f) {
            float is = __fdividef(1.0f, sx);
            float t0 = (-1.0f - bx) * is, t1 = (128.0f - bx) * is;
            lo_k = fmaxf(lo_k, fminf(t0, t1));
            hi_k = fminf(hi_k, fmaxf(t0, t1));
        } else if (bx < -1.0f || bx > 128.0f) { lo_k = 1.0f; hi_k = 0.0f; }
    }
    int kmin = max(0, (int)ceilf(lo_k));
    int kmax = min(DVOL - 1, (int)floorf(hi_k));

    // Balanced split of [kmin, kmax] across the 4 warps.
    int len   = kmax - kmin + 1;
    int chunk = (len + 3) >> 2;
    int qlo   = kmin + q * chunk;
    int qhi   = min(qlo + chunk - 1, kmax);

    // Shifted coordinates: fz' = fz + 3 in [2, 131] (magic-safe).
    float bzp = bz + 3.0f;
    float bxp = bx + 3.0f;

    // Bias-folded base pointer (entry stride 8B).
    const char* bias_base = (const char*)g_H
                          + (size_t)qlo * (size_t)(BPL2 * 8)
                          - ((size_t)OFF_BIAS << 3);

    float accA = 0.0f, accB = 0.0f;
    float kf = (float)qlo;
    int k = qlo;

    const __half2 hzero = __floats2half2_rn(0.0f, 0.0f);

    // Batched-by-4: address gen, 4 independent LDG.64s, half-precision lerp,
    // flush the half accumulator to fp32 once per batch (keeps |hacc| small).
    for (; k + 3 <= qhi; k += 4, bias_base += 4 * (size_t)(BPL2 * 8)) {
        unsigned offv[4];
        float wzv[4], wxv[4];
        #pragma unroll
        for (int u = 0; u < 4; ++u) {
            float fzp = fmaf(kf, sz, bzp);
            float fxp = fmaf(kf, sx, bxp);
            kf += 1.0f;
            float mz = fzp + MAGICH;           // 2^23 + floor(fz')
            float mx = fxp + MAGICH;
            unsigned mzb = (unsigned)__float_as_int(mz);
            unsigned mxb = (unsigned)__float_as_int(mx);
            wzv[u] = fzp - (mz - MAGIC);
            wxv[u] = fxp - (mx - MAGIC);
            offv[u] = mzb * (unsigned)BW2 + mxb;   // zi*134+xi+OFF_BIAS (mod 2^32)
        }
        uint2 cv[4];
        #pragma unroll
        for (int u = 0; u < 4; ++u)
            cv[u] = __ldg((const uint2*)(bias_base + (size_t)u * (BPL2 * 8)
                                         + ((size_t)offv[u] << 3)));
        __half2 hacc = hzero;
        #pragma unroll
        for (int u = 0; u < 4; ++u) {
            __half2 reg0 = *reinterpret_cast<__half2*>(&cv[u].x);  // (e0, e2)
            __half2 reg1 = *reinterpret_cast<__half2*>(&cv[u].y);  // (e1, e3)
            __half2 wxh  = __floats2half2_rn(wxv[u], wxv[u]);
            __half2 w2   = __floats2half2_rn(1.0f, wzv[u]);
            __half2 th   = __hfma2(wxh, reg1, reg0);   // (t0, t1)
            hacc = __hfma2(w2, th, hacc);              // (Σt0, Σwz·t1)
        }
        float2 f = __half22float2(hacc);
        accA += f.x;
        accB += f.y;
    }
    for (; k <= qhi; ++k, bias_base += (size_t)(BPL2 * 8)) {
        float fzp = fmaf(kf, sz, bzp);
        float fxp = fmaf(kf, sx, bxp);
        kf += 1.0f;
        float mz = fzp + MAGICH;
        float mx = fxp + MAGICH;
        unsigned mzb = (unsigned)__float_as_int(mz);
        unsigned mxb = (unsigned)__float_as_int(mx);
        float wz = fzp - (mz - MAGIC);
        float wx = fxp - (mx - MAGIC);
        unsigned off = mzb * (unsigned)BW2 + mxb;
        uint2 c = __ldg((const uint2*)(bias_base + ((size_t)off << 3)));
        __half2 reg0 = *reinterpret_cast<__half2*>(&c.x);
        __half2 reg1 = *reinterpret_cast<__half2*>(&c.y);
        float2 e02 = __half22float2(reg0);
        float2 e13 = __half22float2(reg1);
        float t0 = fmaf(wx, e13.x, e02.x);
        float t1 = fmaf(wx, e13.y, e02.y);
        accA += t0;
        accB  = fmaf(wz, t1, accB);
    }

    part[q][lane] = accA + accB;
    __syncthreads();

    if (q == 0 && valid) {
        float s = part[0][lane] + part[1][lane] + part[2][lane] + part[3][lane];
        out[p_pix] = s * dxw;
    }
}

extern "C" void kernel_launch(void* const* d_in, const int* in_sizes, int n_in,
                              void* d_out, int out_size) {
    const float* vol   = (const float*)d_in[0];   // I_rec: 1*1*128*128*128 f32
    const float* poses = (const float*)d_in[1];   // 50*3 f32
    const int*   idx   = (const int*)d_in[2];     // 10 i32
    float* out = (float*)d_out;

    build_H_kernel<<<(ETOT + 255) / 256, 256>>>(vol);

    int tail = out_size - NPIX;
    if (tail < 0) tail = 0;
    if (tail > 1024) tail = 1024;
    project_kernel<<<NGRP + 1, 128>>>(poses, idx, out, tail);
}

// round 10
// speedup vs baseline: 1.3422x; 1.0958x over previous
#include <cuda_runtime.h>
#include <cuda_fp16.h>

// Problem constants (fixed by the reference)
#define DVOL   128
#define RES    179
#define NPROJ  10
#define PIX    (RES * RES)          // 32041
#define NPIX   (NPROJ * PIX)        // 320410
#define BW2    134                  // padded extent of zi/xi (0..133), z0 = zi-3
#define BPL2   (BW2 * BW2)          // 17956 entries per k-plane
#define ETOT   (DVOL * BPL2)        // 2,298,368 entries
#define HTOT   (ETOT / 2)           // build threads (2 entries each)
#define NGRP   ((NPIX + 31) / 32)   // 10013 pixel groups of 32

#define MAGIC      8388608.0f       // 2^23
#define MAGICH     8388607.5f       // 2^23 - 0.5  (floor via RNE(g - 0.5))
// bits(2^23 + n) = 0x4B000000 + n for n in [0,2^23).
// Fallback path: bits(mz)*134 + bits(mx) = zi*134 + xi + 0x8D000000 (mod 2^32).
#define OFF_BIAS   0x8D000000u
// Fast path: rowidx = k*BPL2 + bits(mz)*134 + 0x73000000; idx = rowidx + bits(mx)
//   biases: 0x4B000000*134 = 0x42000000, +0x73000000 = 0xB5000000,
//           + 0x4B000000 (from bits(mx)) = 0x100000000 ≡ 0  ✓
#define ROW_BIAS   0x73000000u

// fp16 bilinear-coefficient table (zero guard band of 3 on each side):
//   entry.x = half2(e0, e2), entry.y = half2(e1, e3)
//   e0=c00, e1=c01-c00, e2=c10-c00, e3=c11-c01-c10+c00
// with c_ab = A[z0+a][x0+b], z0 = zi-3, x0 = xi-3,
//      A[z][x] = 0.5*(vol[z][k-1][x] + vol[z][k][x]) (vol[.,-1,.] = 0),
//      A = 0 outside z,x in [0,127].
// sample = (e0 + wx*e1) + wz*(e2 + wx*e3)
__device__ uint2 g_H[ETOT];         // ≈ 18.4 MB (L2-resident)

__device__ __forceinline__ float Aval(const float* __restrict__ vol,
                                      int z, int x, int k, int km, bool hk) {
    if ((unsigned)z >= 128u || (unsigned)x >= 128u) return 0.0f;
    const float* pk = vol + (z * DVOL + k)  * DVOL;
    float v = __ldg(pk + x);
    if (hk) v += __ldg(vol + (z * DVOL + km) * DVOL + x);
    return 0.5f * v;
}

__device__ __forceinline__ unsigned pack_h2(float a, float b) {
    __half2 h = __floats2half2_rn(a, b);
    return *reinterpret_cast<const unsigned*>(&h);
}

// Each thread emits TWO adjacent-xi entries (they share a corner column).
__global__ void __launch_bounds__(256) build_H_kernel(const float* __restrict__ vol) {
    int t = blockIdx.x * blockDim.x + threadIdx.x;
    if (t >= HTOT) return;
    const int HPL = BPL2 / 2;       // 8978
    int k   = t / HPL;
    int rem = t - k * HPL;
    int zi  = rem / (BW2 / 2);      // 0..133
    int m   = rem - zi * (BW2 / 2); // 0..66
    int z0  = zi - 3;
    int c0  = 2 * m - 3;            // columns c0, c0+1, c0+2
    bool hk = (k > 0);
    int  km = hk ? k - 1 : 0;

    float a00 = Aval(vol, z0,     c0,     k, km, hk);
    float a01 = Aval(vol, z0,     c0 + 1, k, km, hk);
    float a02 = Aval(vol, z0,     c0 + 2, k, km, hk);
    float a10 = Aval(vol, z0 + 1, c0,     k, km, hk);
    float a11 = Aval(vol, z0 + 1, c0 + 1, k, km, hk);
    float a12 = Aval(vol, z0 + 1, c0 + 2, k, km, hk);

    uint4 v;
    // entry xi=2m: corners (a00,a01 / a10,a11)
    v.x = pack_h2(a00, a10 - a00);
    v.y = pack_h2(a01 - a00, a11 - a01 - a10 + a00);
    // entry xi=2m+1: corners (a01,a02 / a11,a12)
    v.z = pack_h2(a01, a11 - a01);
    v.w = pack_h2(a02 - a01, a12 - a02 - a11 + a01);

    *reinterpret_cast<uint4*>(g_H + (size_t)k * BPL2 + zi * BW2 + 2 * m) = v;
}

// Block = 128 threads = 32 pixels (one per lane) x 4 balanced k-chunks (one per warp).
__global__ void __launch_bounds__(128) project_kernel(
    const float* __restrict__ poses,
    const int*   __restrict__ idx,
    float*       __restrict__ out,
    int tail)
{
    __shared__ float part[4][33];
    __shared__ uint2 ktab[128];      // fast path: (half2(1,wz), bias-folded rowidx)

    int g = blockIdx.x;
    if (g == NGRP) {                 // dedicated tail block: write idx appendix
        for (int u = threadIdx.x; u < tail; u += 128)
            out[NPIX + u] = (u < NPROJ) ? (float)__ldg(&idx[u]) : 0.0f;
        return;
    }

    int lane = threadIdx.x & 31;
    int q    = threadIdx.x >> 5;     // k-chunk index

    int p_pix = g * 32 + lane;
    bool valid = p_pix < NPIX;
    int pp  = valid ? p_pix : NPIX - 1;
    int p   = pp / PIX;
    int rem = pp - p * PIX;
    int i   = rem / RES;             // detector row (gx)
    int j   = rem - i * RES;         // detector col (gy) — contiguous per lane

    // Block-uniformity: all 32 pixels share (p, i)?
    int first = g * 32, last = g * 32 + 31;
    bool unif = (last < NPIX)
             && (first / PIX == last / PIX)
             && ((first % PIX) / RES == (last % PIX) / RES);

    int e = __ldg(&idx[p]);
    float ex = __ldg(&poses[e * 3 + 0]);
    float ey = __ldg(&poses[e * 3 + 1]);
    float ez = __ldg(&poses[e * 3 + 2]);

    float gx = (float)i - 89.5f;
    float gy = (float)j - 89.5f;

    // Unnormalized ray; normalization cancels except in the dx weight.
    float rx = gx - ex;
    float ry = -ey;                  // detector plane is y = 0
    float rz = gy - ez;
    float n  = sqrtf(rx * rx + ry * ry + rz * rz);
    float inv_ry = __fdividef(1.0f, ry);
    float dxw = fabsf(inv_ry) * n;

    // Sample position at plane k (volume index space), linear in k.
    float sz = rx * inv_ry;
    float sx = rz * inv_ry;
    float bz = fmaf(-ey, sz, ex + 63.5f);
    float bx = fmaf(-ey, sx, ez + 63.5f);

    // Trim to fz,fx in [-1, 128]: outside this both stencil rows/cols hit the
    // zero-padded region, so dropped samples contribute exactly zero.
    float lo_k = 0.0f, hi_k = 127.0f;
    {
        if (fabsf(sz) > 1e-12f) {
            float is = __fdividef(1.0f, sz);
            float t0 = (-1.0f - bz) * is, t1 = (128.0f - bz) * is;
            lo_k = fmaxf(lo_k, fminf(t0, t1));
            hi_k = fminf(hi_k, fmaxf(t0, t1));
        } else if (bz < -1.0f || bz > 128.0f) { lo_k = 1.0f; hi_k = 0.0f; }
        if (fabsf(sx) > 1e-12f) {
            float is = __fdividef(1.0f, sx);
            float t0 = (-1.0f - bx) * is, t1 = (128.0f - bx) * is;
            lo_k = fmaxf(lo_k, fminf(t0, t1));
            hi_k = fminf(hi_k, fmaxf(t0, t1));
        } else if (bx < -1.0f || bx > 128.0f) { lo_k = 1.0f; hi_k = 0.0f; }
    }
    int kmin = max(0, (int)ceilf(lo_k));
    int kmax = min(DVOL - 1, (int)floorf(hi_k));

    // Balanced split of [kmin, kmax] across the 4 warps.
    int len   = kmax - kmin + 1;
    int chunk = (len + 3) >> 2;
    int qlo   = kmin + q * chunk;
    int qhi   = min(qlo + chunk - 1, kmax);

    // Shifted coordinates: fz' = fz + 3 in [2, 131] (magic-safe) on used k.
    float bzp = bz + 3.0f;
    float bxp = bx + 3.0f;

    float accA = 0.0f, accB = 0.0f;

    if (unif) {
        // ── fast path: z-chain is lane-uniform -> precompute per-k table ──
        {
            int kk = threadIdx.x;            // 128 threads = 128 k values
            float fzp = fmaf((float)kk, sz, bzp);
            float mz  = fzp + MAGICH;
            float zif = mz - MAGIC;
            float wz  = fzp - zif;
            unsigned rowidx = (unsigned)kk * (unsigned)BPL2
                            + (unsigned)__float_as_int(mz) * (unsigned)BW2
                            + ROW_BIAS;
            ktab[kk] = make_uint2(pack_h2(1.0f, wz), rowidx);
        }
        __syncthreads();

        float kf = (float)qlo;
        int k = qlo;
        for (; k + 3 <= qhi; k += 4) {
            uint2 ktv[4];
            unsigned offv[4];
            float wxv[4];
            #pragma unroll
            for (int u = 0; u < 4; ++u) ktv[u] = ktab[k + u];
            #pragma unroll
            for (int u = 0; u < 4; ++u) {
                float fxp = fmaf(kf, sx, bxp);
                kf += 1.0f;
                float mx  = fxp + MAGICH;
                float xif = mx - MAGIC;
                wxv[u]  = fxp - xif;
                offv[u] = ktv[u].y + (unsigned)__float_as_int(mx);
            }
            uint2 cv[4];
            #pragma unroll
            for (int u = 0; u < 4; ++u) cv[u] = __ldg(&g_H[offv[u]]);
            __half2 hacc = __floats2half2_rn(0.0f, 0.0f);
            #pragma unroll
            for (int u = 0; u < 4; ++u) {
                __half2 reg0 = *reinterpret_cast<__half2*>(&cv[u].x);
                __half2 reg1 = *reinterpret_cast<__half2*>(&cv[u].y);
                __half2 wxh  = __floats2half2_rn(wxv[u], wxv[u]);
                __half2 w2   = *reinterpret_cast<__half2*>(&ktv[u].x);
                __half2 th   = __hfma2(wxh, reg1, reg0);
                hacc = __hfma2(w2, th, hacc);
            }
            float2 f = __half22float2(hacc);
            accA += f.x;
            accB += f.y;
        }
        for (; k <= qhi; ++k) {
            uint2 kt = ktab[k];
            float fxp = fmaf(kf, sx, bxp);
            kf += 1.0f;
            float mx  = fxp + MAGICH;
            float xif = mx - MAGIC;
            float wx  = fxp - xif;
            unsigned off = kt.y + (unsigned)__float_as_int(mx);
            uint2 c = __ldg(&g_H[off]);
            __half2 reg0 = *reinterpret_cast<__half2*>(&c.x);
            __half2 reg1 = *reinterpret_cast<__half2*>(&c.y);
            float2 e02 = __half22float2(reg0);
            float2 e13 = __half22float2(reg1);
            float wzf;
            {
                __half2 w2 = *reinterpret_cast<__half2*>(&kt.x);
                wzf = __high2float(w2);
            }
            float t0 = fmaf(wx, e13.x, e02.x);
            float t1 = fmaf(wx, e13.y, e02.y);
            accA += t0;
            accB  = fmaf(wzf, t1, accB);
        }
    } else {
        // ── fallback: proven per-lane path (R9) ──
        const char* bias_base = (const char*)g_H
                              + (size_t)qlo * (size_t)(BPL2 * 8)
                              - ((size_t)OFF_BIAS << 3);
        float kf = (float)qlo;
        int k = qlo;
        for (; k + 3 <= qhi; k += 4, bias_base += 4 * (size_t)(BPL2 * 8)) {
            unsigned offv[4];
            float wzv[4], wxv[4];
            #pragma unroll
            for (int u = 0; u < 4; ++u) {
                float fzp = fmaf(kf, sz, bzp);
                float fxp = fmaf(kf, sx, bxp);
                kf += 1.0f;
                float mz = fzp + MAGICH;
                float mx = fxp + MAGICH;
                unsigned mzb = (unsigned)__float_as_int(mz);
                unsigned mxb = (unsigned)__float_as_int(mx);
                wzv[u] = fzp - (mz - MAGIC);
                wxv[u] = fxp - (mx - MAGIC);
                offv[u] = mzb * (unsigned)BW2 + mxb;
            }
            uint2 cv[4];
            #pragma unroll
            for (int u = 0; u < 4; ++u)
                cv[u] = __ldg((const uint2*)(bias_base + (size_t)u * (BPL2 * 8)
                                             + ((size_t)offv[u] << 3)));
            __half2 hacc = __floats2half2_rn(0.0f, 0.0f);
            #pragma unroll
            for (int u = 0; u < 4; ++u) {
                __half2 reg0 = *reinterpret_cast<__half2*>(&cv[u].x);
                __half2 reg1 = *reinterpret_cast<__half2*>(&cv[u].y);
                __half2 wxh  = __floats2half2_rn(wxv[u], wxv[u]);
                __half2 w2   = __floats2half2_rn(1.0f, wzv[u]);
                __half2 th   = __hfma2(wxh, reg1, reg0);
                hacc = __hfma2(w2, th, hacc);
            }
            float2 f = __half22float2(hacc);
            accA += f.x;
            accB += f.y;
        }
        for (; k <= qhi; ++k, bias_base += (size_t)(BPL2 * 8)) {
            float fzp = fmaf(kf, sz, bzp);
            float fxp = fmaf(kf, sx, bxp);
            kf += 1.0f;
            float mz = fzp + MAGICH;
            float mx = fxp + MAGICH;
            unsigned mzb = (unsigned)__float_as_int(mz);
            unsigned mxb = (unsigned)__float_as_int(mx);
            float wz = fzp - (mz - MAGIC);
            float wx = fxp - (mx - MAGIC);
            unsigned off = mzb * (unsigned)BW2 + mxb;
            uint2 c = __ldg((const uint2*)(bias_base + ((size_t)off << 3)));
            __half2 reg0 = *reinterpret_cast<__half2*>(&c.x);
            __half2 reg1 = *reinterpret_cast<__half2*>(&c.y);
            float2 e02 = __half22float2(reg0);
            float2 e13 = __half22float2(reg1);
            float t0 = fmaf(wx, e13.x, e02.x);
            float t1 = fmaf(wx, e13.y, e02.y);
            accA += t0;
            accB  = fmaf(wz, t1, accB);
        }
    }

    part[q][lane] = accA + accB;
    __syncthreads();

    if (q == 0 && valid) {
        float s = part[0][lane] + part[1][lane] + part[2][lane] + part[3][lane];
        out[p_pix] = s * dxw;
    }
}

extern "C" void kernel_launch(void* const* d_in, const int* in_sizes, int n_in,
                              void* d_out, int out_size) {
    const float* vol   = (const float*)d_in[0];   // I_rec: 1*1*128*128*128 f32
    const float* poses = (const float*)d_in[1];   // 50*3 f32
    const int*   idx   = (const int*)d_in[2];     // 10 i32
    float* out = (float*)d_out;

    build_H_kernel<<<(HTOT + 255) / 256, 256>>>(vol);

    int tail = out_size - NPIX;
    if (tail < 0) tail = 0;
    if (tail > 1024) tail = 1024;
    project_kernel<<<NGRP + 1, 128>>>(poses, idx, out, tail);
}

// round 11
// speedup vs baseline: 1.4581x; 1.0863x over previous
#include <cuda_runtime.h>
#include <cuda_fp16.h>

// Problem constants (fixed by the reference)
#define DVOL   128
#define RES    179
#define NPROJ  10
#define PIX    (RES * RES)          // 32041
#define NPIX   (NPROJ * PIX)        // 320410
#define BW2    134                  // padded extent of zi/xi (0..133), z0 = zi-3
#define BPL2   (BW2 * BW2)          // 17956 entries per k-plane
#define ETOT   (DVOL * BPL2)        // 2,298,368 entries
#define NGRP   ((NPIX + 31) / 32)   // 10013 pixel groups of 32

// build: one thread emits a 2x2 entry block (shares a 3x3 A stencil)
#define QROWS  67                   // zi pairs (0..133)
#define QCOLS  67                   // xi pairs
#define QPL    (QROWS * QCOLS)      // 4489 per plane
#define QTOT   (DVOL * QPL)         // 574,592 threads

#define MAGIC      8388608.0f       // 2^23
#define MAGICH     8388607.5f       // 2^23 - 0.5  (floor via RNE(g - 0.5))
// bits(2^23 + n) = 0x4B000000 + n for n in [0,2^23).
// Fallback: bits(mz)*134 + bits(mx) = zi*134 + xi + 0x8D000000 (mod 2^32).
#define OFF_BIAS   0x8D000000u
// Fast path: rowidx = k*BPL2 + bits(mz)*134 + 0x73000000; idx = rowidx + bits(mx)
//   0x4B000000*134 + 0x73000000 + 0x4B000000 = 0x100000000 ≡ 0 (mod 2^32) ✓
#define ROW_BIAS   0x73000000u

// fp16 bilinear-coefficient table (zero guard band of 3 on each side):
//   entry.x = half2(e0, e2), entry.y = half2(e1, e3)
//   e0=c00, e1=c01-c00, e2=c10-c00, e3=c11-c01-c10+c00
// with c_ab = A[z0+a][x0+b], z0 = zi-3, x0 = xi-3,
//      A[z][x] = 0.5*(vol[z][k-1][x] + vol[z][k][x]) (vol[.,-1,.] = 0),
//      A = 0 outside z,x in [0,127].
// sample = (e0 + wx*e1) + wz*(e2 + wx*e3)
__device__ uint2 g_H[ETOT];         // ≈ 18.4 MB (L2-resident)

__device__ __forceinline__ float Aval(const float* __restrict__ vol,
                                      int z, int x, int k, int km, bool hk) {
    if ((unsigned)z >= 128u || (unsigned)x >= 128u) return 0.0f;
    const float* pk = vol + (z * DVOL + k)  * DVOL;
    float v = __ldg(pk + x);
    if (hk) v += __ldg(vol + (z * DVOL + km) * DVOL + x);
    return 0.5f * v;
}

__device__ __forceinline__ unsigned pack_h2(float a, float b) {
    __half2 h = __floats2half2_rn(a, b);
    return *reinterpret_cast<const unsigned*>(&h);
}

__device__ __forceinline__ uint2 make_entry(float c00, float c01,
                                            float c10, float c11) {
    uint2 v;
    v.x = pack_h2(c00, c10 - c00);
    v.y = pack_h2(c01 - c00, c11 - c01 - c10 + c00);
    return v;
}

// Each thread emits a 2x2 block of entries (zi,zi+1)x(xi,xi+1), zi,xi even.
__global__ void __launch_bounds__(256) build_H_kernel(const float* __restrict__ vol) {
    int t = blockIdx.x * blockDim.x + threadIdx.x;
    if (t >= QTOT) return;
    int k   = t / QPL;
    int rem = t - k * QPL;
    int zr  = rem / QCOLS;
    int xr  = rem - zr * QCOLS;
    int zi  = 2 * zr;               // 0..132
    int xi  = 2 * xr;
    bool hk = (k > 0);
    int  km = hk ? k - 1 : 0;

    // 3x3 A stencil: rows zi-3..zi-1, cols xi-3..xi-1
    float a[3][3];
    #pragma unroll
    for (int r = 0; r < 3; ++r)
        #pragma unroll
        for (int c = 0; c < 3; ++c)
            a[r][c] = Aval(vol, zi - 3 + r, xi - 3 + c, k, km, hk);

    uint2 e00 = make_entry(a[0][0], a[0][1], a[1][0], a[1][1]); // (zi,   xi)
    uint2 e01 = make_entry(a[0][1], a[0][2], a[1][1], a[1][2]); // (zi,   xi+1)
    uint2 e10 = make_entry(a[1][0], a[1][1], a[2][0], a[2][1]); // (zi+1, xi)
    uint2 e11 = make_entry(a[1][1], a[1][2], a[2][1], a[2][2]); // (zi+1, xi+1)

    size_t base = (size_t)k * BPL2 + (size_t)zi * BW2 + xi;
    *reinterpret_cast<uint4*>(g_H + base)       = make_uint4(e00.x, e00.y, e01.x, e01.y);
    *reinterpret_cast<uint4*>(g_H + base + BW2) = make_uint4(e10.x, e10.y, e11.x, e11.y);
}

// Block = 128 threads = 32 pixels (one per lane) x 4 balanced k-chunks (one per warp).
__global__ void __launch_bounds__(128) project_kernel(
    const float* __restrict__ poses,
    const int*   __restrict__ idx,
    float*       __restrict__ out,
    int tail)
{
    __shared__ float part[4][33];
    __shared__ uint2 ktab[128];      // fast path: (half2(1,wz), bias-folded rowidx)

    int g = blockIdx.x;
    if (g == NGRP) {                 // dedicated tail block: write idx appendix
        for (int u = threadIdx.x; u < tail; u += 128)
            out[NPIX + u] = (u < NPROJ) ? (float)__ldg(&idx[u]) : 0.0f;
        return;
    }

    int lane = threadIdx.x & 31;
    int q    = threadIdx.x >> 5;     // k-chunk index

    int p_pix = g * 32 + lane;
    bool valid = p_pix < NPIX;
    int pp  = valid ? p_pix : NPIX - 1;
    int p   = pp / PIX;
    int rem = pp - p * PIX;
    int i   = rem / RES;             // detector row (gx)
    int j   = rem - i * RES;         // detector col (gy) — contiguous per lane

    // Block-uniformity: all 32 pixels share (p, i)?
    int first = g * 32, last = g * 32 + 31;
    bool unif = (last < NPIX)
             && (first / PIX == last / PIX)
             && ((first % PIX) / RES == (last % PIX) / RES);

    int e = __ldg(&idx[p]);
    float ex = __ldg(&poses[e * 3 + 0]);
    float ey = __ldg(&poses[e * 3 + 1]);
    float ez = __ldg(&poses[e * 3 + 2]);

    float gx = (float)i - 89.5f;
    float gy = (float)j - 89.5f;

    // Unnormalized ray; normalization cancels except in the dx weight.
    float rx = gx - ex;
    float ry = -ey;                  // detector plane is y = 0
    float rz = gy - ez;
    float n  = sqrtf(rx * rx + ry * ry + rz * rz);
    float inv_ry = __fdividef(1.0f, ry);
    float dxw = fabsf(inv_ry) * n;

    // Sample position at plane k (volume index space), linear in k.
    float sz = rx * inv_ry;
    float sx = rz * inv_ry;
    float bz = fmaf(-ey, sz, ex + 63.5f);
    float bx = fmaf(-ey, sx, ez + 63.5f);

    // Trim to fz,fx in [-1, 128]: outside this both stencil rows/cols hit the
    // zero-padded region, so dropped samples contribute exactly zero.
    float lo_k = 0.0f, hi_k = 127.0f;
    {
        if (fabsf(sz) > 1e-12f) {
            float is = __fdividef(1.0f, sz);
            float t0 = (-1.0f - bz) * is, t1 = (128.0f - bz) * is;
            lo_k = fmaxf(lo_k, fminf(t0, t1));
            hi_k = fminf(hi_k, fmaxf(t0, t1));
        } else if (bz < -1.0f || bz > 128.0f) { lo_k = 1.0f; hi_k = 0.0f; }
        if (fabsf(sx) > 1e-12f) {
            float is = __fdividef(1.0f, sx);
            float t0 = (-1.0f - bx) * is, t1 = (128.0f - bx) * is;
            lo_k = fmaxf(lo_k, fminf(t0, t1));
            hi_k = fminf(hi_k, fmaxf(t0, t1));
        } else if (bx < -1.0f || bx > 128.0f) { lo_k = 1.0f; hi_k = 0.0f; }
    }
    int kmin = max(0, (int)ceilf(lo_k));
    int kmax = min(DVOL - 1, (int)floorf(hi_k));

    // Balanced split of [kmin, kmax] across the 4 warps.
    int len   = kmax - kmin + 1;
    int chunk = (len + 3) >> 2;
    int qlo   = kmin + q * chunk;
    int qhi   = min(qlo + chunk - 1, kmax);

    // Shifted coordinates: fz' = fz + 3 in [2, 131] (magic-safe) on used k.
    float bzp = bz + 3.0f;
    float bxp = bx + 3.0f;

    float accA = 0.0f, accB = 0.0f;

    if (unif) {
        // ── fast path: z-chain is lane-uniform -> per-k table in smem ──
        {
            int kk = threadIdx.x;            // 128 threads = 128 k values
            float fzp = fmaf((float)kk, sz, bzp);
            float mz  = fzp + MAGICH;
            float zif = mz - MAGIC;
            float wz  = fzp - zif;
            unsigned rowidx = (unsigned)kk * (unsigned)BPL2
                            + (unsigned)__float_as_int(mz) * (unsigned)BW2
                            + ROW_BIAS;
            ktab[kk] = make_uint2(pack_h2(1.0f, wz), rowidx);
        }
        __syncthreads();

        float fxp = fmaf((float)qlo, sx, bxp);   // incremental thereafter
        int k = qlo;
        for (; k + 3 <= qhi; k += 4) {
            uint2 ktv[4];
            unsigned offv[4];
            float wxv[4];
            #pragma unroll
            for (int u = 0; u < 4; ++u) ktv[u] = ktab[k + u];
            #pragma unroll
            for (int u = 0; u < 4; ++u) {
                float mx  = fxp + MAGICH;
                float xif = mx - MAGIC;
                wxv[u]  = fxp - xif;
                offv[u] = ktv[u].y + (unsigned)__float_as_int(mx);
                fxp += sx;
            }
            uint2 cv[4];
            #pragma unroll
            for (int u = 0; u < 4; ++u) cv[u] = __ldg(&g_H[offv[u]]);
            __half2 hacc = __floats2half2_rn(0.0f, 0.0f);
            #pragma unroll
            for (int u = 0; u < 4; ++u) {
                __half2 reg0 = *reinterpret_cast<__half2*>(&cv[u].x);
                __half2 reg1 = *reinterpret_cast<__half2*>(&cv[u].y);
                __half2 wxh  = __floats2half2_rn(wxv[u], wxv[u]);
                __half2 w2   = *reinterpret_cast<__half2*>(&ktv[u].x);
                __half2 th   = __hfma2(wxh, reg1, reg0);
                hacc = __hfma2(w2, th, hacc);
            }
            float2 f = __half22float2(hacc);
            accA += f.x;
            accB += f.y;
        }
        for (; k <= qhi; ++k) {
            uint2 kt = ktab[k];
            float mx  = fxp + MAGICH;
            float xif = mx - MAGIC;
            float wx  = fxp - xif;
            fxp += sx;
            unsigned off = kt.y + (unsigned)__float_as_int(mx);
            uint2 c = __ldg(&g_H[off]);
            __half2 reg0 = *reinterpret_cast<__half2*>(&c.x);
            __half2 reg1 = *reinterpret_cast<__half2*>(&c.y);
            float2 e02 = __half22float2(reg0);
            float2 e13 = __half22float2(reg1);
            __half2 w2 = *reinterpret_cast<__half2*>(&kt.x);
            float wzf  = __high2float(w2);
            float t0 = fmaf(wx, e13.x, e02.x);
            float t1 = fmaf(wx, e13.y, e02.y);
            accA += t0;
            accB  = fmaf(wzf, t1, accB);
        }
    } else {
        // ── fallback: per-lane path ──
        const char* bias_base = (const char*)g_H
                              + (size_t)qlo * (size_t)(BPL2 * 8)
                              - ((size_t)OFF_BIAS << 3);
        float fzp = fmaf((float)qlo, sz, bzp);
        float fxp = fmaf((float)qlo, sx, bxp);
        int k = qlo;
        for (; k + 3 <= qhi; k += 4, bias_base += 4 * (size_t)(BPL2 * 8)) {
            unsigned offv[4];
            float wzv[4], wxv[4];
            #pragma unroll
            for (int u = 0; u < 4; ++u) {
                float mz = fzp + MAGICH;
                float mx = fxp + MAGICH;
                unsigned mzb = (unsigned)__float_as_int(mz);
                unsigned mxb = (unsigned)__float_as_int(mx);
                wzv[u] = fzp - (mz - MAGIC);
                wxv[u] = fxp - (mx - MAGIC);
                offv[u] = mzb * (unsigned)BW2 + mxb;
                fzp += sz;
                fxp += sx;
            }
            uint2 cv[4];
            #pragma unroll
            for (int u = 0; u < 4; ++u)
                cv[u] = __ldg((const uint2*)(bias_base + (size_t)u * (BPL2 * 8)
                                             + ((size_t)offv[u] << 3)));
            __half2 hacc = __floats2half2_rn(0.0f, 0.0f);
            #pragma unroll
            for (int u = 0; u < 4; ++u) {
                __half2 reg0 = *reinterpret_cast<__half2*>(&cv[u].x);
                __half2 reg1 = *reinterpret_cast<__half2*>(&cv[u].y);
                __half2 wxh  = __floats2half2_rn(wxv[u], wxv[u]);
                __half2 w2   = __floats2half2_rn(1.0f, wzv[u]);
                __half2 th   = __hfma2(wxh, reg1, reg0);
                hacc = __hfma2(w2, th, hacc);
            }
            float2 f = __half22float2(hacc);
            accA += f.x;
            accB += f.y;
        }
        for (; k <= qhi; ++k, bias_base += (size_t)(BPL2 * 8)) {
            float mz = fzp + MAGICH;
            float mx = fxp + MAGICH;
            unsigned mzb = (unsigned)__float_as_int(mz);
            unsigned mxb = (unsigned)__float_as_int(mx);
            float wz = fzp - (mz - MAGIC);
            float wx = fxp - (mx - MAGIC);
            fzp += sz;
            fxp += sx;
            unsigned off = mzb * (unsigned)BW2 + mxb;
            uint2 c = __ldg((const uint2*)(bias_base + ((size_t)off << 3)));
            __half2 reg0 = *reinterpret_cast<__half2*>(&c.x);
            __half2 reg1 = *reinterpret_cast<__half2*>(&c.y);
            float2 e02 = __half22float2(reg0);
            float2 e13 = __half22float2(reg1);
            float t0 = fmaf(wx, e13.x, e02.x);
            float t1 = fmaf(wx, e13.y, e02.y);
            accA += t0;
            accB  = fmaf(wz, t1, accB);
        }
    }

    part[q][lane] = accA + accB;
    __syncthreads();

    if (q == 0 && valid) {
        float s = part[0][lane] + part[1][lane] + part[2][lane] + part[3][lane];
        out[p_pix] = s * dxw;
    }
}

extern "C" void kernel_launch(void* const* d_in, const int* in_sizes, int n_in,
                              void* d_out, int out_size) {
    const float* vol   = (const float*)d_in[0];   // I_rec: 1*1*128*128*128 f32
    const float* poses = (const float*)d_in[1];   // 50*3 f32
    const int*   idx   = (const int*)d_in[2];     // 10 i32
    float* out = (float*)d_out;

    build_H_kernel<<<(QTOT + 255) / 256, 256>>>(vol);

    int tail = out_size - NPIX;
    if (tail < 0) tail = 0;
    if (tail > 1024) tail = 1024;
    project_kernel<<<NGRP + 1, 128>>>(poses, idx, out, tail);
}